// round 2
// baseline (speedup 1.0000x reference)
#include <cuda_runtime.h>
#include <cuda_bf16.h>
#include <math.h>
#include <stdint.h>

typedef __nv_bfloat16 bf16;

#define BATCH 8
#define CDIM  768
#define HDIM  56
#define WDIM  56
#define LDIM  3136
#define BL    25088
#define FEPS  1e-6f
#define BNEPS 1e-5f
#define CC    (CDIM*CDIM)
#define NCHUNK 16          // L-split for deterministic reduction
#define LCHUNK (LDIM/NCHUNK)   // 196

// ---------------- scratch (device globals; no runtime allocation) ----------------
__device__ __align__(16) float g_pos[LDIM*CDIM];
__device__ __align__(16) float g_t  [(size_t)BL*CDIM];
__device__ __align__(16) bf16  g_tbf[(size_t)BL*CDIM];
__device__ __align__(16) bf16  g_w  [5*CC];
__device__ __align__(16) float g_Q  [(size_t)BL*CDIM];
__device__ __align__(16) float g_K  [(size_t)BL*CDIM];
__device__ __align__(16) float g_V  [(size_t)BL*CDIM];
__device__ __align__(16) bf16  g_Q1 [(size_t)BL*CDIM];
__device__ __align__(16) bf16  g_K1 [(size_t)BL*CDIM];
__device__ __align__(16) float g_kvp[NCHUNK*BATCH*CDIM];
__device__ __align__(16) float g_ksp[NCHUNK*BATCH*CDIM];
__device__ __align__(16) float g_kv [BATCH*CDIM];
__device__ __align__(16) float g_ks [BATCH*CDIM];
__device__ __align__(16) float g_logits[(size_t)BATCH*CC];
__device__ __align__(16) bf16  g_mid[(size_t)BATCH*CC];
__device__ __align__(16) bf16  g_res[(size_t)BL*CDIM];
__device__ __align__(16) float g_tt [(size_t)BL*CDIM];   // t + gamma*res2

// ---------------- PTX helpers ----------------
__device__ __forceinline__ uint32_t smem_u32(const void* p){
    return (uint32_t)__cvta_generic_to_shared(p);
}
__device__ __forceinline__ void cp16(void* s, const void* g){
    asm volatile("cp.async.cg.shared.global [%0], [%1], 16;\n"
                 :: "r"(smem_u32(s)), "l"(g));
}
__device__ __forceinline__ void cp_commit(){ asm volatile("cp.async.commit_group;\n"); }
template<int N> __device__ __forceinline__ void cp_wait(){
    asm volatile("cp.async.wait_group %0;\n" :: "n"(N));
}
__device__ __forceinline__ void ldsm_x4(uint32_t* r, uint32_t addr){
    asm volatile("ldmatrix.sync.aligned.m8n8.x4.shared.b16 {%0,%1,%2,%3},[%4];\n"
                 : "=r"(r[0]),"=r"(r[1]),"=r"(r[2]),"=r"(r[3]) : "r"(addr));
}
__device__ __forceinline__ void ldsm_x4t(uint32_t* r, uint32_t addr){
    asm volatile("ldmatrix.sync.aligned.m8n8.x4.trans.shared.b16 {%0,%1,%2,%3},[%4];\n"
                 : "=r"(r[0]),"=r"(r[1]),"=r"(r[2]),"=r"(r[3]) : "r"(addr));
}
__device__ __forceinline__ void mma16816(float* c, const uint32_t* a, const uint32_t* b){
    asm volatile(
        "mma.sync.aligned.m16n8k16.row.col.f32.bf16.bf16.f32 "
        "{%0,%1,%2,%3},{%4,%5,%6,%7},{%8,%9},{%0,%1,%2,%3};\n"
        : "+f"(c[0]),"+f"(c[1]),"+f"(c[2]),"+f"(c[3])
        : "r"(a[0]),"r"(a[1]),"r"(a[2]),"r"(a[3]),"r"(b[0]),"r"(b[1]));
}

// ================= pos encoding: g_pos[l, c] =================
__global__ void pos_kernel(const float* __restrict__ pos_w, const float* __restrict__ pos_b){
    __shared__ float feat[64];
    int l = blockIdx.x;
    int h = l / WDIM, w = l % WDIM;
    int tid = threadIdx.x;
    if (tid < 64){
        int k = tid & 31;
        bool isY = tid < 32;
        float scale = 6.2831853071795864769f / (56.0f + FEPS);
        float v = (isY ? (float)(h + 1) : (float)(w + 1)) * scale;
        int j = k >> 1;
        float D = powf(10000.0f, (float)j * (1.0f/16.0f));
        float p = v / D;
        feat[tid] = (k & 1) ? cosf(p) : sinf(p);
    }
    __syncthreads();
    for (int c = tid; c < CDIM; c += 256){
        float s = pos_b[c];
        #pragma unroll
        for (int k = 0; k < 64; k++) s += feat[k] * pos_w[k*CDIM + c];
        g_pos[(size_t)l*CDIM + c] = s;
    }
}

// ================= weights -> bf16 =================
__global__ void wconv_kernel(const float* __restrict__ wq, const float* __restrict__ wk,
                             const float* __restrict__ wv, const float* __restrict__ wq1,
                             const float* __restrict__ wk1){
    int i = blockIdx.x*256 + threadIdx.x;
    int z = i / CC, j = i % CC;
    const float* src = (z==0)?wq:(z==1)?wk:(z==2)?wv:(z==3)?wq1:wk1;
    g_w[i] = __float2bfloat16(src[j]);
}

// ================= build t = transpose(x) + pos =================
__global__ void build_t_kernel(const float* __restrict__ x){
    __shared__ float tile[32][33];
    int b = blockIdx.z;
    int l0 = blockIdx.x*32, c0 = blockIdx.y*32;
    int tx = threadIdx.x, ty = threadIdx.y;
    const float* xp = x + (size_t)b*CDIM*LDIM;
    #pragma unroll
    for (int i = 0; i < 4; i++){
        int cc = ty + i*8;
        tile[cc][tx] = xp[(size_t)(c0+cc)*LDIM + l0 + tx];
    }
    __syncthreads();
    #pragma unroll
    for (int i = 0; i < 4; i++){
        int lrow = ty + i*8;
        int l = l0 + lrow, c = c0 + tx;
        float v = tile[tx][lrow] + g_pos[(size_t)l*CDIM + c];
        size_t idx = ((size_t)b*LDIM + l)*CDIM + c;
        g_t[idx]   = v;
        g_tbf[idx] = __float2bfloat16(v);
    }
}

// ================= GEMM: 5 projections (z selects weight/epilogue) =================
// C[m,n] = t[m,:] @ w[:,n], m over BL, tiles 128x128x32, 8 warps
__global__ __launch_bounds__(256) void gemm_proj_kernel(
    const float* __restrict__ bq, const float* __restrict__ bk,
    const float* __restrict__ bv, const float* __restrict__ bq1,
    const float* __restrict__ bk1)
{
    int z = blockIdx.z;
    const bf16* A = g_tbf;
    const bf16* B = g_w + (size_t)z*CC;
    const float* bias = (z==0)?bq:(z==1)?bk:(z==2)?bv:(z==3)?bq1:bk1;
    int m0 = blockIdx.x*128, n0 = blockIdx.y*128;
    __shared__ bf16 As[2][128*40];
    __shared__ bf16 Bs[2][32*136];
    int tid = threadIdx.x;
    float acc[4][4][4];
    #pragma unroll
    for (int a=0;a<4;a++) for (int b2=0;b2<4;b2++) for (int c=0;c<4;c++) acc[a][b2][c]=0.f;

    // prologue load kt=0
    {
        #pragma unroll
        for (int i=0;i<2;i++){
            int row = tid/4 + i*64, ch = tid&3;
            cp16(&As[0][row*40 + ch*8], A + (size_t)(m0+row)*CDIM + ch*8);
        }
        #pragma unroll
        for (int i=0;i<2;i++){
            int row = tid/16 + i*16, ch = tid&15;
            cp16(&Bs[0][row*136 + ch*8], B + (size_t)row*CDIM + n0 + ch*8);
        }
        cp_commit();
    }
    const int KT = CDIM/32;
    int warp = tid>>5, lane = tid&31;
    int wm = warp>>2, wn = warp&3;
    for (int kt = 0; kt < KT; kt++){
        int cur = kt & 1;
        if (kt+1 < KT){
            int nxt = cur^1, kb = (kt+1)*32;
            #pragma unroll
            for (int i=0;i<2;i++){
                int row = tid/4 + i*64, ch = tid&3;
                cp16(&As[nxt][row*40 + ch*8], A + (size_t)(m0+row)*CDIM + kb + ch*8);
            }
            #pragma unroll
            for (int i=0;i<2;i++){
                int row = tid/16 + i*16, ch = tid&15;
                cp16(&Bs[nxt][row*136 + ch*8], B + (size_t)(kb+row)*CDIM + n0 + ch*8);
            }
            cp_commit();
            cp_wait<1>();
        } else cp_wait<0>();
        __syncthreads();
        #pragma unroll
        for (int kf = 0; kf < 2; kf++){
            uint32_t a[4][4];
            #pragma unroll
            for (int mf=0; mf<4; mf++){
                int r = lane & 15, ccn = lane >> 4;
                ldsm_x4(a[mf], smem_u32(&As[cur][(wm*64+mf*16+r)*40 + kf*16 + ccn*8]));
            }
            uint32_t b[4][2];
            #pragma unroll
            for (int np=0; np<2; np++){
                int k = kf*16 + (lane&7) + ((lane>>3)&1)*8;
                int noff = (lane>>4)*8;
                uint32_t r4[4];
                ldsm_x4t(r4, smem_u32(&Bs[cur][k*136 + wn*32 + np*16 + noff]));
                b[np*2][0]=r4[0]; b[np*2][1]=r4[1];
                b[np*2+1][0]=r4[2]; b[np*2+1][1]=r4[3];
            }
            #pragma unroll
            for (int mf=0; mf<4; mf++)
                #pragma unroll
                for (int nf=0; nf<4; nf++)
                    mma16816(acc[mf][nf], a[mf], b[nf]);
        }
        __syncthreads();
    }
    // epilogue
    int rbase = m0 + wm*64 + (lane>>2);
    int cbase = n0 + wn*32 + (lane&3)*2;
    if (z <= 2){
        float* Out = (z==0)?g_Q:(z==1)?g_K:g_V;
        bool relu = (z<2);
        #pragma unroll
        for (int mf=0; mf<4; mf++)
            #pragma unroll
            for (int nf=0; nf<4; nf++){
                int r = rbase + mf*16, c = cbase + nf*8;
                float b0 = bias[c], b1 = bias[c+1];
                float v0 = acc[mf][nf][0]+b0, v1 = acc[mf][nf][1]+b1;
                float v2 = acc[mf][nf][2]+b0, v3 = acc[mf][nf][3]+b1;
                if (relu){ v0=fmaxf(v0,0.f); v1=fmaxf(v1,0.f); v2=fmaxf(v2,0.f); v3=fmaxf(v3,0.f); }
                Out[(size_t)r*CDIM + c] = v0;     Out[(size_t)r*CDIM + c+1] = v1;
                Out[(size_t)(r+8)*CDIM + c] = v2; Out[(size_t)(r+8)*CDIM + c+1] = v3;
            }
    } else {
        bf16* Out = (z==3)?g_Q1:g_K1;
        #pragma unroll
        for (int mf=0; mf<4; mf++)
            #pragma unroll
            for (int nf=0; nf<4; nf++){
                int r = rbase + mf*16, c = cbase + nf*8;
                float b0 = bias[c], b1 = bias[c+1];
                __nv_bfloat162 p0, p1;
                p0.x = __float2bfloat16(acc[mf][nf][0]+b0);
                p0.y = __float2bfloat16(acc[mf][nf][1]+b1);
                p1.x = __float2bfloat16(acc[mf][nf][2]+b0);
                p1.y = __float2bfloat16(acc[mf][nf][3]+b1);
                *reinterpret_cast<__nv_bfloat162*>(&Out[(size_t)r*CDIM + c]) = p0;
                *reinterpret_cast<__nv_bfloat162*>(&Out[(size_t)(r+8)*CDIM + c]) = p1;
            }
    }
}

// ================= kv_diag / ksum reductions =================
__global__ void red1_kernel(){
    int ct = blockIdx.x, chunk = blockIdx.y, b = blockIdx.z;
    int c = ct*128 + threadIdx.x;
    int l0 = chunk * LCHUNK;
    float skv = 0.f, sk = 0.f;
    for (int l = l0; l < l0 + LCHUNK; l++){
        size_t idx = ((size_t)b*LDIM + l)*CDIM + c;
        float kk = g_K[idx], vv = g_V[idx];
        skv += kk*vv; sk += kk;
    }
    int o = (chunk*BATCH + b)*CDIM + c;
    g_kvp[o] = skv; g_ksp[o] = sk;
}
__global__ void red2_kernel(){
    int i = blockIdx.x*256 + threadIdx.x;   // i = b*CDIM + c, total BATCH*CDIM
    float skv = 0.f, sk = 0.f;
    #pragma unroll
    for (int ch = 0; ch < NCHUNK; ch++){
        skv += g_kvp[ch*BATCH*CDIM + i];
        sk  += g_ksp[ch*BATCH*CDIM + i];
    }
    g_kv[i] = skv; g_ks[i] = sk;
}

// ================= z + res (bf16) =================
__global__ __launch_bounds__(256) void zres_kernel(){
    int warp = threadIdx.x >> 5, lane = threadIdx.x & 31;
    int r = blockIdx.x*8 + warp;          // r in [0, BL)
    int b = r / LDIM;
    const float* qrow = g_Q + (size_t)r*CDIM;
    const float* ks = g_ks + b*CDIM;
    const float* kv = g_kv + b*CDIM;
    float s = 0.f;
    for (int c = lane; c < CDIM; c += 32) s += qrow[c]*(ks[c] + FEPS);
    #pragma unroll
    for (int o = 16; o > 0; o >>= 1) s += __shfl_xor_sync(0xffffffffu, s, o);
    float zv = 1.0f / s;
    for (int c = lane; c < CDIM; c += 32)
        g_res[(size_t)r*CDIM + c] = __float2bfloat16(qrow[c]*kv[c]*zv);
}

// ================= logits = Q1^T @ K1 per batch (TN) =================
__global__ __launch_bounds__(256) void gemm_logits_kernel(){
    int b = blockIdx.z;
    int m0 = blockIdx.x*128, n0 = blockIdx.y*128;
    const bf16* A = g_Q1 + (size_t)b*LDIM*CDIM;   // [l][c]
    const bf16* B = g_K1 + (size_t)b*LDIM*CDIM;   // [l][d]
    __shared__ bf16 As[2][32*136];
    __shared__ bf16 Bs[2][32*136];
    int tid = threadIdx.x;
    float acc[4][4][4];
    #pragma unroll
    for (int a=0;a<4;a++) for (int b2=0;b2<4;b2++) for (int c=0;c<4;c++) acc[a][b2][c]=0.f;
    {
        #pragma unroll
        for (int i=0;i<2;i++){
            int row = tid/16 + i*16, ch = tid&15;
            cp16(&As[0][row*136 + ch*8], A + (size_t)row*CDIM + m0 + ch*8);
            cp16(&Bs[0][row*136 + ch*8], B + (size_t)row*CDIM + n0 + ch*8);
        }
        cp_commit();
    }
    const int KT = LDIM/32;   // 98
    int warp = tid>>5, lane = tid&31;
    int wm = warp>>2, wn = warp&3;
    for (int kt = 0; kt < KT; kt++){
        int cur = kt & 1;
        if (kt+1 < KT){
            int nxt = cur^1, kb = (kt+1)*32;
            #pragma unroll
            for (int i=0;i<2;i++){
                int row = tid/16 + i*16, ch = tid&15;
                cp16(&As[nxt][row*136 + ch*8], A + (size_t)(kb+row)*CDIM + m0 + ch*8);
                cp16(&Bs[nxt][row*136 + ch*8], B + (size_t)(kb+row)*CDIM + n0 + ch*8);
            }
            cp_commit();
            cp_wait<1>();
        } else cp_wait<0>();
        __syncthreads();
        #pragma unroll
        for (int kf = 0; kf < 2; kf++){
            int kA = kf*16 + (lane&7) + ((lane>>3)>=2 ? 8 : 0);
            int moff = ((lane>>3)&1)*8;
            uint32_t a[4][4];
            #pragma unroll
            for (int mf=0; mf<4; mf++)
                ldsm_x4t(a[mf], smem_u32(&As[cur][kA*136 + wm*64 + mf*16 + moff]));
            uint32_t b[4][2];
            #pragma unroll
            for (int np=0; np<2; np++){
                int k = kf*16 + (lane&7) + ((lane>>3)&1)*8;
                int noff = (lane>>4)*8;
                uint32_t r4[4];
                ldsm_x4t(r4, smem_u32(&Bs[cur][k*136 + wn*32 + np*16 + noff]));
                b[np*2][0]=r4[0]; b[np*2][1]=r4[1];
                b[np*2+1][0]=r4[2]; b[np*2+1][1]=r4[3];
            }
            #pragma unroll
            for (int mf=0; mf<4; mf++)
                #pragma unroll
                for (int nf=0; nf<4; nf++)
                    mma16816(acc[mf][nf], a[mf], b[nf]);
        }
        __syncthreads();
    }
    float* Out = g_logits + (size_t)b*CC;
    int rbase = m0 + wm*64 + (lane>>2);
    int cbase = n0 + wn*32 + (lane&3)*2;
    #pragma unroll
    for (int mf=0; mf<4; mf++)
        #pragma unroll
        for (int nf=0; nf<4; nf++){
            int r = rbase + mf*16, c = cbase + nf*8;
            Out[(size_t)r*CDIM + c]     = acc[mf][nf][0];
            Out[(size_t)r*CDIM + c+1]   = acc[mf][nf][1];
            Out[(size_t)(r+8)*CDIM + c]   = acc[mf][nf][2];
            Out[(size_t)(r+8)*CDIM + c+1] = acc[mf][nf][3];
        }
}

// ================= softmax over last dim -> bf16 mid =================
__global__ __launch_bounds__(256) void softmax_kernel(){
    __shared__ float sred[256];
    const float* row = g_logits + (size_t)blockIdx.x*CDIM;
    int tid = threadIdx.x;
    float m = -3.0e38f;
    #pragma unroll
    for (int j = 0; j < 3; j++) m = fmaxf(m, row[tid + j*256]);
    sred[tid] = m; __syncthreads();
    for (int s = 128; s > 0; s >>= 1){
        if (tid < s) sred[tid] = fmaxf(sred[tid], sred[tid+s]);
        __syncthreads();
    }
    m = sred[0]; __syncthreads();
    float e[3]; float s = 0.f;
    #pragma unroll
    for (int j = 0; j < 3; j++){ e[j] = expf(row[tid + j*256] - m); s += e[j]; }
    sred[tid] = s; __syncthreads();
    for (int st = 128; st > 0; st >>= 1){
        if (tid < st) sred[tid] += sred[tid+st];
        __syncthreads();
    }
    float inv = 1.0f / sred[0];
    bf16* out = g_mid + (size_t)blockIdx.x*CDIM;
    #pragma unroll
    for (int j = 0; j < 3; j++) out[tid + j*256] = __float2bfloat16(e[j]*inv);
}

// ================= res2 = res @ mid (per batch), fused tt = t + gamma*res2 =================
// BM=64, BN=128, BK=32
__global__ __launch_bounds__(256) void gemm_res_kernel(const float* __restrict__ gptr){
    int b = blockIdx.z;
    int m0 = blockIdx.x*64, n0 = blockIdx.y*128;
    const bf16* A = g_res + ((size_t)b*LDIM + m0)*CDIM;
    const bf16* B = g_mid + (size_t)b*CC;
    __shared__ bf16 As[2][64*40];
    __shared__ bf16 Bs[2][32*136];
    int tid = threadIdx.x;
    float acc[2][4][4];
    #pragma unroll
    for (int a=0;a<2;a++) for (int b2=0;b2<4;b2++) for (int c=0;c<4;c++) acc[a][b2][c]=0.f;
    {
        int row = tid/4, ch = tid&3;
        cp16(&As[0][row*40 + ch*8], A + (size_t)row*CDIM + ch*8);
        #pragma unroll
        for (int i=0;i<2;i++){
            int rw = tid/16 + i*16, cb = tid&15;
            cp16(&Bs[0][rw*136 + cb*8], B + (size_t)rw*CDIM + n0 + cb*8);
        }
        cp_commit();
    }
    const int KT = CDIM/32;
    int warp = tid>>5, lane = tid&31;
    int wm = warp>>2, wn = warp&3;
    for (int kt = 0; kt < KT; kt++){
        int cur = kt & 1;
        if (kt+1 < KT){
            int nxt = cur^1, kb = (kt+1)*32;
            int row = tid/4, ch = tid&3;
            cp16(&As[nxt][row*40 + ch*8], A + (size_t)row*CDIM + kb + ch*8);
            #pragma unroll
            for (int i=0;i<2;i++){
                int rw = tid/16 + i*16, cb = tid&15;
                cp16(&Bs[nxt][rw*136 + cb*8], B + (size_t)(kb+rw)*CDIM + n0 + cb*8);
            }
            cp_commit();
            cp_wait<1>();
        } else cp_wait<0>();
        __syncthreads();
        #pragma unroll
        for (int kf = 0; kf < 2; kf++){
            uint32_t a[2][4];
            #pragma unroll
            for (int mf=0; mf<2; mf++){
                int r = lane & 15, ccn = lane >> 4;
                ldsm_x4(a[mf], smem_u32(&As[cur][(wm*32+mf*16+r)*40 + kf*16 + ccn*8]));
            }
            uint32_t b[4][2];
            #pragma unroll
            for (int np=0; np<2; np++){
                int k = kf*16 + (lane&7) + ((lane>>3)&1)*8;
                int noff = (lane>>4)*8;
                uint32_t r4[4];
                ldsm_x4t(r4, smem_u32(&Bs[cur][k*136 + wn*32 + np*16 + noff]));
                b[np*2][0]=r4[0]; b[np*2][1]=r4[1];
                b[np*2+1][0]=r4[2]; b[np*2+1][1]=r4[3];
            }
            #pragma unroll
            for (int mf=0; mf<2; mf++)
                #pragma unroll
                for (int nf=0; nf<4; nf++)
                    mma16816(acc[mf][nf], a[mf], b[nf]);
        }
        __syncthreads();
    }
    float gam = gptr[0];
    int rbase = wm*32 + (lane>>2);
    int cbase = n0 + wn*32 + (lane&3)*2;
    #pragma unroll
    for (int mf=0; mf<2; mf++)
        #pragma unroll
        for (int nf=0; nf<4; nf++){
            int rl = rbase + mf*16, c = cbase + nf*8;
            size_t g0 = ((size_t)b*LDIM + m0 + rl)*CDIM + c;
            size_t g1 = ((size_t)b*LDIM + m0 + rl + 8)*CDIM + c;
            g_tt[g0]   = g_t[g0]   + gam*acc[mf][nf][0];
            g_tt[g0+1] = g_t[g0+1] + gam*acc[mf][nf][1];
            g_tt[g1]   = g_t[g1]   + gam*acc[mf][nf][2];
            g_tt[g1+1] = g_t[g1+1] + gam*acc[mf][nf][3];
        }
}

// ================= BN + relu + transpose out =================
__global__ void bnout_kernel(const float* __restrict__ bn_w, const float* __restrict__ bn_b,
                             const float* __restrict__ bn_mean, const float* __restrict__ bn_var,
                             float* __restrict__ out){
    __shared__ float tile[32][33];
    int b = blockIdx.z;
    int l0 = blockIdx.x*32, c0 = blockIdx.y*32;
    int tx = threadIdx.x, ty = threadIdx.y;
    #pragma unroll
    for (int i = 0; i < 4; i++){
        int lrow = ty + i*8;
        tile[lrow][tx] = g_tt[((size_t)b*LDIM + l0 + lrow)*CDIM + c0 + tx];
    }
    __syncthreads();
    #pragma unroll
    for (int i = 0; i < 4; i++){
        int crow = ty + i*8;
        int c = c0 + crow, l = l0 + tx;
        float scale = bn_w[c] * rsqrtf(bn_var[c] + BNEPS);
        float shift = bn_b[c] - bn_mean[c]*scale;
        float v = tile[tx][crow]*scale + shift;
        out[((size_t)b*CDIM + c)*LDIM + l] = fmaxf(v, 0.f);
    }
}

// ================= launch =================
extern "C" void kernel_launch(void* const* d_in, const int* in_sizes, int n_in,
                              void* d_out, int out_size){
    const float* x     = (const float*)d_in[0];
    const float* wq    = (const float*)d_in[1];
    const float* bq    = (const float*)d_in[2];
    const float* wk    = (const float*)d_in[3];
    const float* bk    = (const float*)d_in[4];
    const float* wv    = (const float*)d_in[5];
    const float* bv    = (const float*)d_in[6];
    const float* wq1   = (const float*)d_in[7];
    const float* bq1   = (const float*)d_in[8];
    const float* wk1   = (const float*)d_in[9];
    const float* bk1   = (const float*)d_in[10];
    const float* gamma = (const float*)d_in[11];
    const float* bn_w  = (const float*)d_in[12];
    const float* bn_b  = (const float*)d_in[13];
    const float* bn_m  = (const float*)d_in[14];
    const float* bn_v  = (const float*)d_in[15];
    const float* pos_w = (const float*)d_in[16];
    const float* pos_b = (const float*)d_in[17];
    float* out = (float*)d_out;

    pos_kernel<<<LDIM, 256>>>(pos_w, pos_b);
    wconv_kernel<<<(5*CC)/256, 256>>>(wq, wk, wv, wq1, wk1);
    build_t_kernel<<<dim3(LDIM/32, CDIM/32, BATCH), dim3(32,8)>>>(x);
    gemm_proj_kernel<<<dim3(BL/128, CDIM/128, 5), 256>>>(bq, bk, bv, bq1, bk1);
    red1_kernel<<<dim3(CDIM/128, NCHUNK, BATCH), 128>>>();
    red2_kernel<<<(BATCH*CDIM)/256, 256>>>();
    zres_kernel<<<BL/8, 256>>>();
    gemm_logits_kernel<<<dim3(CDIM/128, CDIM/128, BATCH), 256>>>();
    softmax_kernel<<<BATCH*CDIM, 256>>>();
    gemm_res_kernel<<<dim3(LDIM/64, CDIM/128, BATCH), 256>>>(gamma);
    bnout_kernel<<<dim3(LDIM/32, CDIM/32, BATCH), dim3(32,8)>>>(bn_w, bn_b, bn_m, bn_v, out);
}

// round 3
// speedup vs baseline: 1.0702x; 1.0702x over previous
#include <cuda_runtime.h>
#include <cuda_bf16.h>
#include <math.h>
#include <stdint.h>

typedef __nv_bfloat16 bf16;

#define BATCH 8
#define CDIM  768
#define HDIM  56
#define WDIM  56
#define LDIM  3136
#define BL    25088
#define FEPS  1e-6f
#define BNEPS 1e-5f
#define CC    (CDIM*CDIM)
#define NCHUNK 16
#define LCHUNK (LDIM/NCHUNK)   // 196

// ---------------- scratch (device globals) ----------------
__device__ __align__(16) float g_pos[LDIM*CDIM];
__device__ __align__(16) float g_t  [(size_t)BL*CDIM];
__device__ __align__(16) bf16  g_tbf[(size_t)BL*CDIM];
__device__ __align__(16) bf16  g_w  [5*CC];
__device__ __align__(16) bf16  g_Q  [(size_t)BL*CDIM];
__device__ __align__(16) bf16  g_K  [(size_t)BL*CDIM];
__device__ __align__(16) bf16  g_V  [(size_t)BL*CDIM];
__device__ __align__(16) bf16  g_Q1 [(size_t)BL*CDIM];
__device__ __align__(16) bf16  g_K1 [(size_t)BL*CDIM];
__device__ __align__(16) float g_kvp[NCHUNK*BATCH*CDIM];
__device__ __align__(16) float g_ksp[NCHUNK*BATCH*CDIM];
__device__ __align__(16) float g_kv [BATCH*CDIM];
__device__ __align__(16) float g_ks [BATCH*CDIM];
__device__ __align__(16) float g_logits[(size_t)BATCH*CC];
__device__ __align__(16) bf16  g_mid[(size_t)BATCH*CC];
__device__ __align__(16) bf16  g_res[(size_t)BL*CDIM];

// ---------------- PTX helpers ----------------
__device__ __forceinline__ uint32_t smem_u32(const void* p){
    return (uint32_t)__cvta_generic_to_shared(p);
}
__device__ __forceinline__ void cp16(void* s, const void* g){
    asm volatile("cp.async.cg.shared.global [%0], [%1], 16;\n"
                 :: "r"(smem_u32(s)), "l"(g));
}
__device__ __forceinline__ void cp_commit(){ asm volatile("cp.async.commit_group;\n"); }
template<int N> __device__ __forceinline__ void cp_wait(){
    asm volatile("cp.async.wait_group %0;\n" :: "n"(N));
}
__device__ __forceinline__ void ldsm_x4(uint32_t* r, uint32_t addr){
    asm volatile("ldmatrix.sync.aligned.m8n8.x4.shared.b16 {%0,%1,%2,%3},[%4];\n"
                 : "=r"(r[0]),"=r"(r[1]),"=r"(r[2]),"=r"(r[3]) : "r"(addr));
}
__device__ __forceinline__ void ldsm_x4t(uint32_t* r, uint32_t addr){
    asm volatile("ldmatrix.sync.aligned.m8n8.x4.trans.shared.b16 {%0,%1,%2,%3},[%4];\n"
                 : "=r"(r[0]),"=r"(r[1]),"=r"(r[2]),"=r"(r[3]) : "r"(addr));
}
__device__ __forceinline__ void mma16816(float* c, const uint32_t* a, const uint32_t* b){
    asm volatile(
        "mma.sync.aligned.m16n8k16.row.col.f32.bf16.bf16.f32 "
        "{%0,%1,%2,%3},{%4,%5,%6,%7},{%8,%9},{%0,%1,%2,%3};\n"
        : "+f"(c[0]),"+f"(c[1]),"+f"(c[2]),"+f"(c[3])
        : "r"(a[0]),"r"(a[1]),"r"(a[2]),"r"(a[3]),"r"(b[0]),"r"(b[1]));
}

// ================= pos encoding =================
__global__ void pos_kernel(const float* __restrict__ pos_w, const float* __restrict__ pos_b){
    __shared__ float feat[64];
    int l = blockIdx.x;
    int h = l / WDIM, w = l % WDIM;
    int tid = threadIdx.x;
    if (tid < 64){
        int k = tid & 31;
        bool isY = tid < 32;
        float scale = 6.2831853071795864769f / (56.0f + FEPS);
        float v = (isY ? (float)(h + 1) : (float)(w + 1)) * scale;
        int j = k >> 1;
        float D = powf(10000.0f, (float)j * (1.0f/16.0f));
        float p = v / D;
        feat[tid] = (k & 1) ? cosf(p) : sinf(p);
    }
    __syncthreads();
    for (int c = tid; c < CDIM; c += 256){
        float s = pos_b[c];
        #pragma unroll
        for (int k = 0; k < 64; k++) s += feat[k] * pos_w[k*CDIM + c];
        g_pos[(size_t)l*CDIM + c] = s;
    }
}

// ================= weights -> bf16 =================
__global__ void wconv_kernel(const float* __restrict__ wq, const float* __restrict__ wk,
                             const float* __restrict__ wv, const float* __restrict__ wq1,
                             const float* __restrict__ wk1){
    int i = blockIdx.x*256 + threadIdx.x;
    int z = i / CC, j = i % CC;
    const float* src = (z==0)?wq:(z==1)?wk:(z==2)?wv:(z==3)?wq1:wk1;
    g_w[i] = __float2bfloat16(src[j]);
}

// ================= build t = transpose(x) + pos =================
__global__ void build_t_kernel(const float* __restrict__ x){
    __shared__ float tile[32][33];
    int b = blockIdx.z;
    int l0 = blockIdx.x*32, c0 = blockIdx.y*32;
    int tx = threadIdx.x, ty = threadIdx.y;
    const float* xp = x + (size_t)b*CDIM*LDIM;
    #pragma unroll
    for (int i = 0; i < 4; i++){
        int cc = ty + i*8;
        tile[cc][tx] = xp[(size_t)(c0+cc)*LDIM + l0 + tx];
    }
    __syncthreads();
    #pragma unroll
    for (int i = 0; i < 4; i++){
        int lrow = ty + i*8;
        int l = l0 + lrow, c = c0 + tx;
        float v = tile[tx][lrow] + g_pos[(size_t)l*CDIM + c];
        size_t idx = ((size_t)b*LDIM + l)*CDIM + c;
        g_t[idx]   = v;
        g_tbf[idx] = __float2bfloat16(v);
    }
}

// ================= 5 projections, 3-stage pipeline =================
#define PROJ_DYN (3*(128*40 + 32*136)*2)
__global__ __launch_bounds__(256) void gemm_proj_kernel(
    const float* __restrict__ bq, const float* __restrict__ bk,
    const float* __restrict__ bv, const float* __restrict__ bq1,
    const float* __restrict__ bk1)
{
    extern __shared__ __align__(16) char dyn[];
    bf16* Asm = (bf16*)dyn;                               // [3][128*40]
    bf16* Bsm = (bf16*)(dyn + 3*128*40*sizeof(bf16));     // [3][32*136]
    int z = blockIdx.z;
    const bf16* A = g_tbf;
    const bf16* B = g_w + (size_t)z*CC;
    const float* bias = (z==0)?bq:(z==1)?bk:(z==2)?bv:(z==3)?bq1:bk1;
    int m0 = blockIdx.x*128, n0 = blockIdx.y*128;
    int tid = threadIdx.x;
    float acc[4][4][4];
    #pragma unroll
    for (int a=0;a<4;a++) for (int b2=0;b2<4;b2++) for (int c=0;c<4;c++) acc[a][b2][c]=0.f;

    const int KT = CDIM/32;   // 24
    // prologue: stages 0,1
    #pragma unroll
    for (int s = 0; s < 2; s++){
        int kb = s*32;
        #pragma unroll
        for (int i=0;i<2;i++){
            int row = tid/4 + i*64, ch = tid&3;
            cp16(&Asm[s*128*40 + row*40 + ch*8], A + (size_t)(m0+row)*CDIM + kb + ch*8);
        }
        #pragma unroll
        for (int i=0;i<2;i++){
            int row = tid/16 + i*16, ch = tid&15;
            cp16(&Bsm[s*32*136 + row*136 + ch*8], B + (size_t)(kb+row)*CDIM + n0 + ch*8);
        }
        cp_commit();
    }
    int warp = tid>>5, lane = tid&31;
    int wm = warp>>2, wn = warp&3;
    for (int kt = 0; kt < KT; kt++){
        cp_wait<1>();
        __syncthreads();
        if (kt+2 < KT){
            int s = (kt+2)%3, kb = (kt+2)*32;
            #pragma unroll
            for (int i=0;i<2;i++){
                int row = tid/4 + i*64, ch = tid&3;
                cp16(&Asm[s*128*40 + row*40 + ch*8], A + (size_t)(m0+row)*CDIM + kb + ch*8);
            }
            #pragma unroll
            for (int i=0;i<2;i++){
                int row = tid/16 + i*16, ch = tid&15;
                cp16(&Bsm[s*32*136 + row*136 + ch*8], B + (size_t)(kb+row)*CDIM + n0 + ch*8);
            }
        }
        cp_commit();
        bf16* Ac = Asm + (kt%3)*128*40;
        bf16* Bc = Bsm + (kt%3)*32*136;
        #pragma unroll
        for (int kf = 0; kf < 2; kf++){
            uint32_t a[4][4];
            #pragma unroll
            for (int mf=0; mf<4; mf++){
                int r = lane & 15, ccn = lane >> 4;
                ldsm_x4(a[mf], smem_u32(&Ac[(wm*64+mf*16+r)*40 + kf*16 + ccn*8]));
            }
            uint32_t b[4][2];
            #pragma unroll
            for (int np=0; np<2; np++){
                int k = kf*16 + (lane&7) + ((lane>>3)&1)*8;
                int noff = (lane>>4)*8;
                uint32_t r4[4];
                ldsm_x4t(r4, smem_u32(&Bc[k*136 + wn*32 + np*16 + noff]));
                b[np*2][0]=r4[0]; b[np*2][1]=r4[1];
                b[np*2+1][0]=r4[2]; b[np*2+1][1]=r4[3];
            }
            #pragma unroll
            for (int mf=0; mf<4; mf++)
                #pragma unroll
                for (int nf=0; nf<4; nf++)
                    mma16816(acc[mf][nf], a[mf], b[nf]);
        }
    }
    // epilogue: all outputs bf16
    bf16* Out = (z==0)?g_Q:(z==1)?g_K:(z==2)?g_V:(z==3)?g_Q1:g_K1;
    bool relu = (z < 2);
    int rbase = m0 + wm*64 + (lane>>2);
    int cbase = n0 + wn*32 + (lane&3)*2;
    #pragma unroll
    for (int mf=0; mf<4; mf++)
        #pragma unroll
        for (int nf=0; nf<4; nf++){
            int r = rbase + mf*16, c = cbase + nf*8;
            float b0 = bias[c], b1 = bias[c+1];
            float v0 = acc[mf][nf][0]+b0, v1 = acc[mf][nf][1]+b1;
            float v2 = acc[mf][nf][2]+b0, v3 = acc[mf][nf][3]+b1;
            if (relu){ v0=fmaxf(v0,0.f); v1=fmaxf(v1,0.f); v2=fmaxf(v2,0.f); v3=fmaxf(v3,0.f); }
            __nv_bfloat162 p0, p1;
            p0.x = __float2bfloat16(v0); p0.y = __float2bfloat16(v1);
            p1.x = __float2bfloat16(v2); p1.y = __float2bfloat16(v3);
            *reinterpret_cast<__nv_bfloat162*>(&Out[(size_t)r*CDIM + c]) = p0;
            *reinterpret_cast<__nv_bfloat162*>(&Out[(size_t)(r+8)*CDIM + c]) = p1;
        }
}

// ================= kv_diag / ksum partial reduction (bf16 in, fp32 out) =================
__global__ void red1_kernel(){
    int c2 = blockIdx.x*128 + threadIdx.x;    // pair index; c = 2*c2
    int chunk = blockIdx.y, b = blockIdx.z;
    const __nv_bfloat162* K2 = (const __nv_bfloat162*)g_K;
    const __nv_bfloat162* V2 = (const __nv_bfloat162*)g_V;
    int l0 = chunk * LCHUNK;
    float skv0=0.f, skv1=0.f, sk0=0.f, sk1=0.f;
    for (int l = l0; l < l0 + LCHUNK; l++){
        size_t idx = ((size_t)b*LDIM + l)*(CDIM/2) + c2;
        __nv_bfloat162 k = K2[idx], v = V2[idx];
        float kx = __bfloat162float(k.x), ky = __bfloat162float(k.y);
        skv0 += kx*__bfloat162float(v.x);
        skv1 += ky*__bfloat162float(v.y);
        sk0 += kx; sk1 += ky;
    }
    int o = (chunk*BATCH + b)*CDIM + 2*c2;
    g_kvp[o] = skv0; g_kvp[o+1] = skv1;
    g_ksp[o] = sk0;  g_ksp[o+1] = sk1;
}
__global__ void red2_kernel(){
    int i = blockIdx.x*256 + threadIdx.x;
    float skv = 0.f, sk = 0.f;
    #pragma unroll
    for (int ch = 0; ch < NCHUNK; ch++){
        skv += g_kvp[ch*BATCH*CDIM + i];
        sk  += g_ksp[ch*BATCH*CDIM + i];
    }
    g_kv[i] = skv; g_ks[i] = sk;
}

// ================= z + res (bf16) =================
__global__ __launch_bounds__(256) void zres_kernel(){
    int warp = threadIdx.x >> 5, lane = threadIdx.x & 31;
    int r = blockIdx.x*8 + warp;
    int b = r / LDIM;
    const __nv_bfloat162* qrow = (const __nv_bfloat162*)(g_Q + (size_t)r*CDIM);
    const float2* ks2 = (const float2*)(g_ks + b*CDIM);
    const float2* kv2 = (const float2*)(g_kv + b*CDIM);
    float s = 0.f;
    #pragma unroll
    for (int i = 0; i < CDIM/64; i++){
        int j = i*32 + lane;
        __nv_bfloat162 q = qrow[j];
        float2 k = ks2[j];
        s += __bfloat162float(q.x)*(k.x+FEPS) + __bfloat162float(q.y)*(k.y+FEPS);
    }
    #pragma unroll
    for (int o = 16; o > 0; o >>= 1) s += __shfl_xor_sync(0xffffffffu, s, o);
    float zv = 1.0f / s;
    __nv_bfloat162* out2 = (__nv_bfloat162*)(g_res + (size_t)r*CDIM);
    #pragma unroll
    for (int i = 0; i < CDIM/64; i++){
        int j = i*32 + lane;
        __nv_bfloat162 q = qrow[j];
        float2 kv = kv2[j];
        __nv_bfloat162 o2;
        o2.x = __float2bfloat16(__bfloat162float(q.x)*kv.x*zv);
        o2.y = __float2bfloat16(__bfloat162float(q.y)*kv.y*zv);
        out2[j] = o2;
    }
}

// ================= logits = Q1^T @ K1 per batch (TN), 3-stage =================
#define LOG_DYN (3*2*(32*136)*2)
__global__ __launch_bounds__(256) void gemm_logits_kernel(){
    extern __shared__ __align__(16) char dyn[];
    bf16* Asm = (bf16*)dyn;                              // [3][32*136]
    bf16* Bsm = (bf16*)(dyn + 3*32*136*sizeof(bf16));    // [3][32*136]
    int b = blockIdx.z;
    int m0 = blockIdx.x*128, n0 = blockIdx.y*128;
    const bf16* A = g_Q1 + (size_t)b*LDIM*CDIM;
    const bf16* B = g_K1 + (size_t)b*LDIM*CDIM;
    int tid = threadIdx.x;
    float acc[4][4][4];
    #pragma unroll
    for (int a=0;a<4;a++) for (int b2=0;b2<4;b2++) for (int c=0;c<4;c++) acc[a][b2][c]=0.f;
    const int KT = LDIM/32;   // 98
    #pragma unroll
    for (int s = 0; s < 2; s++){
        int kb = s*32;
        #pragma unroll
        for (int i=0;i<2;i++){
            int row = tid/16 + i*16, ch = tid&15;
            cp16(&Asm[s*32*136 + row*136 + ch*8], A + (size_t)(kb+row)*CDIM + m0 + ch*8);
            cp16(&Bsm[s*32*136 + row*136 + ch*8], B + (size_t)(kb+row)*CDIM + n0 + ch*8);
        }
        cp_commit();
    }
    int warp = tid>>5, lane = tid&31;
    int wm = warp>>2, wn = warp&3;
    for (int kt = 0; kt < KT; kt++){
        cp_wait<1>();
        __syncthreads();
        if (kt+2 < KT){
            int s = (kt+2)%3, kb = (kt+2)*32;
            #pragma unroll
            for (int i=0;i<2;i++){
                int row = tid/16 + i*16, ch = tid&15;
                cp16(&Asm[s*32*136 + row*136 + ch*8], A + (size_t)(kb+row)*CDIM + m0 + ch*8);
                cp16(&Bsm[s*32*136 + row*136 + ch*8], B + (size_t)(kb+row)*CDIM + n0 + ch*8);
            }
        }
        cp_commit();
        bf16* Ac = Asm + (kt%3)*32*136;
        bf16* Bc = Bsm + (kt%3)*32*136;
        #pragma unroll
        for (int kf = 0; kf < 2; kf++){
            int kA = kf*16 + (lane&7) + ((lane>>3)>=2 ? 8 : 0);
            int moff = ((lane>>3)&1)*8;
            uint32_t a[4][4];
            #pragma unroll
            for (int mf=0; mf<4; mf++)
                ldsm_x4t(a[mf], smem_u32(&Ac[kA*136 + wm*64 + mf*16 + moff]));
            uint32_t b2[4][2];
            #pragma unroll
            for (int np=0; np<2; np++){
                int k = kf*16 + (lane&7) + ((lane>>3)&1)*8;
                int noff = (lane>>4)*8;
                uint32_t r4[4];
                ldsm_x4t(r4, smem_u32(&Bc[k*136 + wn*32 + np*16 + noff]));
                b2[np*2][0]=r4[0]; b2[np*2][1]=r4[1];
                b2[np*2+1][0]=r4[2]; b2[np*2+1][1]=r4[3];
            }
            #pragma unroll
            for (int mf=0; mf<4; mf++)
                #pragma unroll
                for (int nf=0; nf<4; nf++)
                    mma16816(acc[mf][nf], a[mf], b2[nf]);
        }
    }
    float* Out = g_logits + (size_t)b*CC;
    int rbase = m0 + wm*64 + (lane>>2);
    int cbase = n0 + wn*32 + (lane&3)*2;
    #pragma unroll
    for (int mf=0; mf<4; mf++)
        #pragma unroll
        for (int nf=0; nf<4; nf++){
            int r = rbase + mf*16, c = cbase + nf*8;
            Out[(size_t)r*CDIM + c]       = acc[mf][nf][0];
            Out[(size_t)r*CDIM + c+1]     = acc[mf][nf][1];
            Out[(size_t)(r+8)*CDIM + c]   = acc[mf][nf][2];
            Out[(size_t)(r+8)*CDIM + c+1] = acc[mf][nf][3];
        }
}

// ================= softmax -> bf16 mid =================
__global__ __launch_bounds__(256) void softmax_kernel(){
    __shared__ float sred[256];
    const float* row = g_logits + (size_t)blockIdx.x*CDIM;
    int tid = threadIdx.x;
    float m = -3.0e38f;
    #pragma unroll
    for (int j = 0; j < 3; j++) m = fmaxf(m, row[tid + j*256]);
    sred[tid] = m; __syncthreads();
    for (int s = 128; s > 0; s >>= 1){
        if (tid < s) sred[tid] = fmaxf(sred[tid], sred[tid+s]);
        __syncthreads();
    }
    m = sred[0]; __syncthreads();
    float e[3]; float s = 0.f;
    #pragma unroll
    for (int j = 0; j < 3; j++){ e[j] = expf(row[tid + j*256] - m); s += e[j]; }
    sred[tid] = s; __syncthreads();
    for (int st = 128; st > 0; st >>= 1){
        if (tid < st) sred[tid] += sred[tid+st];
        __syncthreads();
    }
    float inv = 1.0f / sred[0];
    bf16* out = g_mid + (size_t)blockIdx.x*CDIM;
    #pragma unroll
    for (int j = 0; j < 3; j++) out[tid + j*256] = __float2bfloat16(e[j]*inv);
}

// ======== res2 = res @ mid; fused: out = relu(BN(t + gamma*res2)) transposed ========
// BM=64, BN=128, BK=32, 3-stage
#define RES_PIPE (3*(64*40 + 32*136)*2)
#define RES_DYN  (RES_PIPE + 128*65*4)
__global__ __launch_bounds__(256) void gemm_res_kernel(
    const float* __restrict__ gptr,
    const float* __restrict__ bn_w, const float* __restrict__ bn_b,
    const float* __restrict__ bn_mean, const float* __restrict__ bn_var,
    float* __restrict__ out)
{
    extern __shared__ __align__(16) char dyn[];
    bf16*  Asm  = (bf16*)dyn;                               // [3][64*40]
    bf16*  Bsm  = (bf16*)(dyn + 3*64*40*sizeof(bf16));      // [3][32*136]
    float* trans = (float*)(dyn + RES_PIPE);                 // [128][65]
    int b = blockIdx.z;
    int m0 = blockIdx.x*64, n0 = blockIdx.y*128;
    const bf16* A = g_res + ((size_t)b*LDIM + m0)*CDIM;
    const bf16* B = g_mid + (size_t)b*CC;
    int tid = threadIdx.x;
    float acc[2][4][4];
    #pragma unroll
    for (int a=0;a<2;a++) for (int b2=0;b2<4;b2++) for (int c=0;c<4;c++) acc[a][b2][c]=0.f;
    const int KT = CDIM/32;
    #pragma unroll
    for (int s = 0; s < 2; s++){
        int kb = s*32;
        {
            int row = tid/4, ch = tid&3;
            cp16(&Asm[s*64*40 + row*40 + ch*8], A + (size_t)row*CDIM + kb + ch*8);
        }
        #pragma unroll
        for (int i=0;i<2;i++){
            int rw = tid/16 + i*16, cb = tid&15;
            cp16(&Bsm[s*32*136 + rw*136 + cb*8], B + (size_t)(kb+rw)*CDIM + n0 + cb*8);
        }
        cp_commit();
    }
    int warp = tid>>5, lane = tid&31;
    int wm = warp>>2, wn = warp&3;
    for (int kt = 0; kt < KT; kt++){
        cp_wait<1>();
        __syncthreads();
        if (kt+2 < KT){
            int s = (kt+2)%3, kb = (kt+2)*32;
            {
                int row = tid/4, ch = tid&3;
                cp16(&Asm[s*64*40 + row*40 + ch*8], A + (size_t)row*CDIM + kb + ch*8);
            }
            #pragma unroll
            for (int i=0;i<2;i++){
                int rw = tid/16 + i*16, cb = tid&15;
                cp16(&Bsm[s*32*136 + rw*136 + cb*8], B + (size_t)(kb+rw)*CDIM + n0 + cb*8);
            }
        }
        cp_commit();
        bf16* Ac = Asm + (kt%3)*64*40;
        bf16* Bc = Bsm + (kt%3)*32*136;
        #pragma unroll
        for (int kf = 0; kf < 2; kf++){
            uint32_t a[2][4];
            #pragma unroll
            for (int mf=0; mf<2; mf++){
                int r = lane & 15, ccn = lane >> 4;
                ldsm_x4(a[mf], smem_u32(&Ac[(wm*32+mf*16+r)*40 + kf*16 + ccn*8]));
            }
            uint32_t b2[4][2];
            #pragma unroll
            for (int np=0; np<2; np++){
                int k = kf*16 + (lane&7) + ((lane>>3)&1)*8;
                int noff = (lane>>4)*8;
                uint32_t r4[4];
                ldsm_x4t(r4, smem_u32(&Bc[k*136 + wn*32 + np*16 + noff]));
                b2[np*2][0]=r4[0]; b2[np*2][1]=r4[1];
                b2[np*2+1][0]=r4[2]; b2[np*2+1][1]=r4[3];
            }
            #pragma unroll
            for (int mf=0; mf<2; mf++)
                #pragma unroll
                for (int nf=0; nf<4; nf++)
                    mma16816(acc[mf][nf], a[mf], b2[nf]);
        }
    }
    // epilogue: tt = t + gamma*res2; BN + relu; stage transposed in smem
    float gam = gptr[0];
    int rbase = wm*32 + (lane>>2);
    int cbase = wn*32 + (lane&3)*2;
    __syncthreads();   // pipeline done; safe to write trans region
    #pragma unroll
    for (int mf=0; mf<2; mf++)
        #pragma unroll
        for (int nf=0; nf<4; nf++){
            int rl = rbase + mf*16;
            int cl = cbase + nf*8;
            #pragma unroll
            for (int half = 0; half < 2; half++){
                int rr = rl + half*8;
                size_t g0 = ((size_t)b*LDIM + m0 + rr)*CDIM + n0 + cl;
                #pragma unroll
                for (int d = 0; d < 2; d++){
                    int c = n0 + cl + d;
                    float scale = bn_w[c] * rsqrtf(bn_var[c] + BNEPS);
                    float shift = bn_b[c] - bn_mean[c]*scale;
                    float tt = g_t[g0 + d] + gam*acc[mf][nf][half*2 + d];
                    trans[(cl + d)*65 + rr] = fmaxf(tt*scale + shift, 0.f);
                }
            }
        }
    __syncthreads();
    #pragma unroll
    for (int it = 0; it < 32; it++){
        int cl = (tid>>6) + it*4;
        int ll = tid & 63;
        out[((size_t)b*CDIM + n0 + cl)*LDIM + m0 + ll] = trans[cl*65 + ll];
    }
}

// ================= launch =================
extern "C" void kernel_launch(void* const* d_in, const int* in_sizes, int n_in,
                              void* d_out, int out_size){
    const float* x     = (const float*)d_in[0];
    const float* wq    = (const float*)d_in[1];
    const float* bq    = (const float*)d_in[2];
    const float* wk    = (const float*)d_in[3];
    const float* bk    = (const float*)d_in[4];
    const float* wv    = (const float*)d_in[5];
    const float* bv    = (const float*)d_in[6];
    const float* wq1   = (const float*)d_in[7];
    const float* bq1   = (const float*)d_in[8];
    const float* wk1   = (const float*)d_in[9];
    const float* bk1   = (const float*)d_in[10];
    const float* gamma = (const float*)d_in[11];
    const float* bn_w  = (const float*)d_in[12];
    const float* bn_b  = (const float*)d_in[13];
    const float* bn_m  = (const float*)d_in[14];
    const float* bn_v  = (const float*)d_in[15];
    const float* pos_w = (const float*)d_in[16];
    const float* pos_b = (const float*)d_in[17];
    float* out = (float*)d_out;

    static bool attr_done = false;
    if (!attr_done){
        cudaFuncSetAttribute(gemm_proj_kernel,   cudaFuncAttributeMaxDynamicSharedMemorySize, PROJ_DYN);
        cudaFuncSetAttribute(gemm_logits_kernel, cudaFuncAttributeMaxDynamicSharedMemorySize, LOG_DYN);
        cudaFuncSetAttribute(gemm_res_kernel,    cudaFuncAttributeMaxDynamicSharedMemorySize, RES_DYN);
        attr_done = true;
    }

    pos_kernel<<<LDIM, 256>>>(pos_w, pos_b);
    wconv_kernel<<<(5*CC)/256, 256>>>(wq, wk, wv, wq1, wk1);
    build_t_kernel<<<dim3(LDIM/32, CDIM/32, BATCH), dim3(32,8)>>>(x);
    gemm_proj_kernel<<<dim3(BL/128, CDIM/128, 5), 256, PROJ_DYN>>>(bq, bk, bv, bq1, bk1);
    red1_kernel<<<dim3(CDIM/256, NCHUNK, BATCH), 128>>>();
    red2_kernel<<<(BATCH*CDIM)/256, 256>>>();
    zres_kernel<<<BL/8, 256>>>();
    gemm_logits_kernel<<<dim3(CDIM/128, CDIM/128, BATCH), 256, LOG_DYN>>>();
    softmax_kernel<<<BATCH*CDIM, 256>>>();
    gemm_res_kernel<<<dim3(LDIM/64, CDIM/128, BATCH), 256, RES_DYN>>>(gamma, bn_w, bn_b, bn_m, bn_v, out);
}